// round 2
// baseline (speedup 1.0000x reference)
#include <cuda_runtime.h>

// ---------------- problem constants ----------------
#define TT   4
#define BB   8
#define NN   32        // T*B
#define CIN  256
#define HH   64
#define WW   64
#define HW   4096
#define K1   192       // conv1 out channels
#define K2   320       // conv2 out channels
#define GRPS 4
#define CG   48        // in channels per group (192/4)
#define KG   80        // out channels per group (320/4)
#define OUTC 512       // K1 + K2

// ---------------- scratch (device globals; no allocation allowed) ----------------
__device__ float g_spikes[(size_t)NN * CIN * HW];   // 134 MB
__device__ float g_y     [(size_t)NN * K1  * HW];   // 100 MB
__device__ float g_yb    [(size_t)NN * K1  * HW];   // 100 MB
__device__ float g_psum  [K1 * NN];                 // BN partial sums (deterministic)
__device__ float g_psq   [K1 * NN];
__device__ float g_mean  [K1];
__device__ float g_istd  [K1];

// ---------------- LIF: v' = v + (x - v)/2 ; s = (v' >= 1); v'' = v' - s ----------------
__global__ void lif_kernel(const float* __restrict__ x) {
    int idx = blockIdx.x * blockDim.x + threadIdx.x;   // over B*CIN*HW = 8388608
    if (idx >= BB * CIN * HW) return;
    float v = 0.0f;
    #pragma unroll
    for (int t = 0; t < TT; t++) {
        float xv = x[(size_t)t * (BB * CIN * HW) + idx];
        v = v + (xv - v) * 0.5f;                 // matches reference rounding exactly
        float s = (v >= 1.0f) ? 1.0f : 0.0f;
        v -= s;                                  // VTH = 1
        g_spikes[(size_t)t * (BB * CIN * HW) + idx] = s;
    }
}

// ---------------- generic 3x3 conv body: 16 oc x (8 rows x 64 cols) per block ----------------
// 128 threads: thread = (oc_half 0..1) x (strip 0..63); strip -> (row 0..7, col0 = 8*(strip&7))
// Per thread: acc[8 oc][8 px]
template <int CC, bool SIGNW>
__device__ __forceinline__ void conv_body(
    const float* __restrict__ in,   // base [cin][HW] for this (n[,group])
    const float* __restrict__ w,    // base for this oc tile: layout [o_local][cin][3][3]
    int cin,
    float* __restrict__ out,        // base for this (n, oc tile): stride HW per channel
    int row0)
{
    __shared__ float s_in[CC][10][66];
    __shared__ float s_w [CC][9][16];

    const int tid    = threadIdx.x;
    const int strip  = tid & 63;
    const int ochalf = tid >> 6;
    const int prow   = strip >> 3;
    const int pcol0  = (strip & 7) * 8;
    const int ocb    = ochalf * 8;

    float acc[8][8];
    #pragma unroll
    for (int o = 0; o < 8; o++)
        #pragma unroll
        for (int p = 0; p < 8; p++) acc[o][p] = 0.0f;

    for (int c0 = 0; c0 < cin; c0 += CC) {
        // load input tile: rows row0-1..row0+8, cols -1..64, CC channels (zero-padded)
        for (int i = tid; i < CC * 10 * 66; i += 128) {
            int cc  = i / 660;
            int rem = i - cc * 660;
            int r   = rem / 66;
            int col = rem - r * 66;
            int gr = row0 - 1 + r;
            int gc = col - 1;
            float v = 0.0f;
            if (gr >= 0 && gr < HH && gc >= 0 && gc < WW)
                v = in[(size_t)(c0 + cc) * HW + gr * WW + gc];
            s_in[cc][r][col] = v;
        }
        // load weights: CC x 9 taps x 16 oc
        for (int i = tid; i < CC * 9 * 16; i += 128) {
            int cc  = i / 144;
            int rem = i - cc * 144;
            int tap = rem >> 4;
            int o   = rem & 15;
            float wv = w[((size_t)o * cin + (c0 + cc)) * 9 + tap];
            if (SIGNW) wv = (wv > 0.0f) ? 1.0f : ((wv < 0.0f) ? -1.0f : 0.0f);
            s_w[cc][tap][o] = wv;
        }
        __syncthreads();

        #pragma unroll
        for (int cc = 0; cc < CC; cc++) {
            #pragma unroll
            for (int ky = 0; ky < 3; ky++) {
                float inv[10];
                #pragma unroll
                for (int j = 0; j < 10; j++)
                    inv[j] = s_in[cc][prow + ky][pcol0 + j];
                #pragma unroll
                for (int kx = 0; kx < 3; kx++) {
                    float wv[8];
                    #pragma unroll
                    for (int o = 0; o < 8; o++)
                        wv[o] = s_w[cc][ky * 3 + kx][ocb + o];
                    #pragma unroll
                    for (int o = 0; o < 8; o++)
                        #pragma unroll
                        for (int p = 0; p < 8; p++)
                            acc[o][p] += wv[o] * inv[p + kx];
                }
            }
        }
        __syncthreads();
    }

    // write 16 oc x 8x64 tile
    #pragma unroll
    for (int o = 0; o < 8; o++) {
        float* op = out + (size_t)(ocb + o) * HW + (row0 + prow) * WW + pcol0;
        #pragma unroll
        for (int p = 0; p < 8; p++) op[p] = acc[o][p];
    }
}

__global__ void __launch_bounds__(128) conv1_kernel(const float* __restrict__ w1) {
    int n = blockIdx.z, oct = blockIdx.y, rt = blockIdx.x;
    conv_body<4, false>(
        g_spikes + (size_t)n * CIN * HW,
        w1 + (size_t)oct * 16 * CIN * 9,
        CIN,
        g_y + ((size_t)n * K1 + oct * 16) * HW,
        rt * 8);
}

__global__ void __launch_bounds__(128) conv2_kernel(const float* __restrict__ w2,
                                                    float* __restrict__ out) {
    int n = blockIdx.z, y = blockIdx.y, rt = blockIdx.x;
    int g = y / 5, oct = y - g * 5;
    int obase = g * KG + oct * 16;
    conv_body<4, true>(
        g_yb + ((size_t)n * K1 + g * CG) * HW,
        w2 + (size_t)obase * CG * 9,
        CG,
        out + ((size_t)n * OUTC + K1 + obase) * HW,
        rt * 8);
}

// ---------------- BN: deterministic two-stage reduction ----------------
__global__ void bn_reduce() {
    int k = blockIdx.x;   // channel
    int n = blockIdx.y;   // image
    const float* p = g_y + ((size_t)n * K1 + k) * HW;
    float s = 0.0f, s2 = 0.0f;
    for (int i = threadIdx.x; i < HW; i += 256) {
        float v = p[i];
        s += v; s2 += v * v;
    }
    __shared__ float rs[256], rq[256];
    rs[threadIdx.x] = s; rq[threadIdx.x] = s2;
    __syncthreads();
    for (int off = 128; off > 0; off >>= 1) {
        if (threadIdx.x < off) {
            rs[threadIdx.x] += rs[threadIdx.x + off];
            rq[threadIdx.x] += rq[threadIdx.x + off];
        }
        __syncthreads();
    }
    if (threadIdx.x == 0) {
        g_psum[k * NN + n] = rs[0];
        g_psq [k * NN + n] = rq[0];
    }
}

__global__ void bn_finalize() {
    int k = threadIdx.x;
    if (k < K1) {
        float s = 0.0f, s2 = 0.0f;
        for (int n = 0; n < NN; n++) { s += g_psum[k * NN + n]; s2 += g_psq[k * NN + n]; }
        const float cnt = (float)(NN * HW);
        float m = s / cnt;
        float var = s2 / cnt - m * m;       // biased variance
        g_mean[k] = m;
        g_istd[k] = rsqrtf(var + 1e-5f);
    }
}

// apply BN; write x1 slice of output and yb scratch (conv2 input)
__global__ void bn_apply(const float* __restrict__ gamma,
                         const float* __restrict__ beta,
                         float* __restrict__ out) {
    int nk = blockIdx.y;                    // n*K1 + k   (0..6143)
    int k  = nk % K1;
    int n  = nk / K1;
    int hw = blockIdx.x * 256 + threadIdx.x;
    float v = g_y[(size_t)nk * HW + hw];
    float r = (v - g_mean[k]) * g_istd[k] * gamma[k] + beta[k];
    g_yb[(size_t)nk * HW + hw] = r;
    out[((size_t)n * OUTC + k) * HW + hw] = r;
}

// ---------------- launch ----------------
extern "C" void kernel_launch(void* const* d_in, const int* in_sizes, int n_in,
                              void* d_out, int out_size) {
    const float* x     = (const float*)d_in[0];
    const float* w1    = (const float*)d_in[1];
    const float* gamma = (const float*)d_in[2];
    const float* beta  = (const float*)d_in[3];
    const float* w2    = (const float*)d_in[4];
    float* out = (float*)d_out;

    lif_kernel<<<(BB * CIN * HW) / 256, 256>>>(x);

    conv1_kernel<<<dim3(8, 12, 32), 128>>>(w1);          // -> g_y

    bn_reduce  <<<dim3(K1, NN), 256>>>();
    bn_finalize<<<1, K1>>>();
    bn_apply   <<<dim3(HW / 256, NN * K1), 256>>>(gamma, beta, out);  // -> x1 + g_yb

    conv2_kernel<<<dim3(8, 20, 32), 128>>>(w2, out);      // -> x2
}

// round 4
// speedup vs baseline: 6.9839x; 6.9839x over previous
#include <cuda_runtime.h>
#include <cuda_bf16.h>
#include <cstdint>

#define NNI 32
#define HW  4096

// ---------------- scratch ----------------
__device__ __align__(128) __nv_bfloat16 g_spk[(size_t)NNI * HW * 256];   // spikes NHWC bf16
__device__ __align__(128) float         g_y  [(size_t)NNI * HW * 192];   // conv1 out NHWC f32
__device__ __align__(128) __nv_bfloat16 g_ybh[(size_t)NNI * HW * 256];   // BN out hi (4x64 padded)
__device__ __align__(128) __nv_bfloat16 g_ybl[(size_t)NNI * HW * 256];   // BN out lo
__device__ __align__(128) __nv_bfloat16 g_wb1[36 * 384 * 64];            // [tap*4+chunk][192hi+192lo][64] swizzled
__device__ __align__(128) __nv_bfloat16 g_wb2[36 * 80 * 64];             // [tap*4+g][80][64] sign, swizzled
__device__ float g_p1[256 * 192], g_p2[256 * 192];
__device__ float g_scale[192], g_shift[192];

// ---------------- PTX helpers (sm_80-compatible only) ----------------
__device__ __forceinline__ uint32_t smem_u32(const void* p) {
    uint32_t a;
    asm("{ .reg .u64 t; cvta.to.shared.u64 t, %1; cvt.u32.u64 %0, t; }" : "=r"(a) : "l"(p));
    return a;
}
#define CP16(dst, src, nb) asm volatile("cp.async.cg.shared.global [%0], [%1], 16, %2;" :: "r"(dst), "l"(src), "r"(nb) : "memory")
#define CP_COMMIT() asm volatile("cp.async.commit_group;" ::: "memory")
#define CP_WAIT(n)  asm volatile("cp.async.wait_group %0;" :: "n"(n) : "memory")

#define LDSM4(r0, r1, r2, r3, addr) \
    asm volatile("ldmatrix.sync.aligned.m8n8.x4.shared.b16 {%0,%1,%2,%3}, [%4];" \
        : "=r"(r0), "=r"(r1), "=r"(r2), "=r"(r3) : "r"(addr))

#define MMA(d, a, b0_, b1_) \
    asm volatile("mma.sync.aligned.m16n8k16.row.col.f32.bf16.bf16.f32 " \
        "{%0,%1,%2,%3}, {%4,%5,%6,%7}, {%8,%9}, {%0,%1,%2,%3};" \
        : "+f"((d)[0]), "+f"((d)[1]), "+f"((d)[2]), "+f"((d)[3]) \
        : "r"((a)[0]), "r"((a)[1]), "r"((a)[2]), "r"((a)[3]), "r"(b0_), "r"(b1_))

// ---------------- LIF -> spikes NHWC bf16 ----------------
__global__ void __launch_bounds__(256) lif_kernel(const float* __restrict__ x) {
    int px = blockIdx.x * 256 + threadIdx.x;
    int cc0 = blockIdx.y * 32, b = blockIdx.z;
    float v[32];
#pragma unroll
    for (int c = 0; c < 32; c++) v[c] = 0.0f;
#pragma unroll
    for (int t = 0; t < 4; t++) {
        const float* xp = x + ((size_t)(t * 8 + b) * 256 + cc0) * HW + px;
        unsigned pk[16];
#pragma unroll
        for (int c = 0; c < 32; c++) {
            float xv = xp[(size_t)c * HW];
            float nv = v[c] + (xv - v[c]) * 0.5f;
            unsigned s = (nv >= 1.0f) ? 0x3F80u : 0u;
            v[c] = nv - ((nv >= 1.0f) ? 1.0f : 0.0f);
            if (c & 1) pk[c >> 1] |= (s << 16); else pk[c >> 1] = s;
        }
        uint4* dst = (uint4*)(g_spk + ((size_t)(t * 8 + b) * HW + px) * 256 + cc0);
#pragma unroll
        for (int q = 0; q < 4; q++) dst[q] = make_uint4(pk[q*4], pk[q*4+1], pk[q*4+2], pk[q*4+3]);
    }
}

// ---------------- weight prep (pre-swizzled gmem tiles) ----------------
__global__ void prep1_kernel(const float* __restrict__ w1) {
    int i = blockIdx.x * 256 + threadIdx.x;           // 36*384*64
    if (i >= 36 * 384 * 64) return;
    int j = i & 63, row = (i >> 6) % 384, it = (i >> 6) / 384;
    int tap = it >> 2, c = (it & 3) * 64 + j;
    int o = (row < 192) ? row : row - 192;
    float w = w1[((size_t)o * 256 + c) * 9 + tap];
    __nv_bfloat16 hi = __float2bfloat16(w);
    __nv_bfloat16 val = (row < 192) ? hi : __float2bfloat16(w - __bfloat162float(hi));
    g_wb1[(size_t)it * 24576 + row * 64 + (((j >> 3) ^ (row & 7)) * 8) + (j & 7)] = val;
}
__global__ void prep2_kernel(const float* __restrict__ w2) {
    int i = blockIdx.x * 256 + threadIdx.x;           // 36*80*64
    if (i >= 36 * 80 * 64) return;
    int j = i & 63, row = (i >> 6) % 80, tg = (i >> 6) / 80;
    int g = tg & 3, tap = tg >> 2;
    float v = 0.0f;
    if (j < 48) {
        float w = w2[(((size_t)(g * 80 + row)) * 48 + j) * 9 + tap];
        v = (w > 0.0f) ? 1.0f : ((w < 0.0f) ? -1.0f : 0.0f);
    }
    g_wb2[(size_t)tg * 5120 + row * 64 + (((j >> 3) ^ (row & 7)) * 8) + (j & 7)] = __float2bfloat16(v);
}

// ---------------- conv1: 128px x 192oc per CTA, K = 36 x 64ch x {hi,lo} ----------------
// smem: A buf0 @0, A buf1 @16384, B buf0 @32768, B buf1 @81920; total 131072
#define C1_SMEM 131072

__device__ __forceinline__ void c1_load(uint32_t sb, int n, int y0, int it, int buf, int tid) {
    int tap = it >> 2, chunk = it & 3;
    int ky = tap / 3, kx = tap % 3;
    const char* spk = (const char*)g_spk;
    uint32_t Ab = sb + (uint32_t)buf * 16384u;
#pragma unroll
    for (int ii = 0; ii < 4; ii++) {
        int lin = tid + ii * 256;
        int row = lin >> 3, j = lin & 7;
        int yy = y0 + (row >> 6) + ky - 1;
        int xg = (row & 63) + kx - 1;
        bool ok = (yy >= 0) & (yy < 64) & (xg >= 0) & (xg < 64);
        size_t off = ((((size_t)n * HW) + (size_t)yy * 64 + xg) * 256 + chunk * 64 + j * 8) * 2;
        CP16(Ab + row * 128 + ((j ^ (row & 7)) << 4), ok ? (spk + off) : spk, ok ? 16 : 0);
    }
    const char* wb = (const char*)(g_wb1 + (size_t)it * 24576);
    uint32_t Bb = sb + 32768u + (uint32_t)buf * 49152u;
#pragma unroll
    for (int ii = 0; ii < 12; ii++) {
        int lin = tid + ii * 256;
        CP16(Bb + lin * 16, wb + lin * 16, 16);
    }
}

__global__ void __launch_bounds__(256, 1) conv1_kernel() {
    extern __shared__ char sm[];
    uint32_t sb = smem_u32(sm);
    int tid = threadIdx.x, l = tid & 31, wid = tid >> 5;
    int wm = wid & 3, wn = wid >> 2;                 // 4 M-warps x 2 N-warps
    int n = blockIdx.x >> 5, y0 = (blockIdx.x & 31) * 2;

    int mat = l >> 3, mr = l & 7;
    int a_rl = (mat & 1) * 8 + mr, a_kh = mat >> 1;  // ldmatrix lane mapping (A)
    int b_nl = (mat >> 1) * 8 + mr, b_kh = mat & 1;  // (B)

    float acc[2][12][4];
#pragma unroll
    for (int i = 0; i < 2; i++)
#pragma unroll
        for (int jn = 0; jn < 12; jn++)
#pragma unroll
            for (int q = 0; q < 4; q++) acc[i][jn][q] = 0.0f;

    c1_load(sb, n, y0, 0, 0, tid); CP_COMMIT();
    for (int it = 0; it < 36; it++) {
        int buf = it & 1;
        if (it < 35) { c1_load(sb, n, y0, it + 1, buf ^ 1, tid); CP_COMMIT(); CP_WAIT(1); }
        else CP_WAIT(0);
        __syncthreads();
        uint32_t Ab = sb + (uint32_t)buf * 16384u;
        uint32_t Bb = sb + 32768u + (uint32_t)buf * 49152u;
#pragma unroll
        for (int ks = 0; ks < 4; ks++) {
            uint32_t a[2][4];
#pragma unroll
            for (int mt = 0; mt < 2; mt++) {
                uint32_t ad = Ab + (uint32_t)((wm * 32 + mt * 16 + a_rl) * 128 +
                                              ((((ks << 1) + a_kh) ^ mr) << 4));
                LDSM4(a[mt][0], a[mt][1], a[mt][2], a[mt][3], ad);
            }
#pragma unroll
            for (int h = 0; h < 2; h++) {
#pragma unroll
                for (int p = 0; p < 6; p++) {
                    int O = wn * 96 + p * 16 + h * 192;
                    uint32_t bd = Bb + (uint32_t)((O + b_nl) * 128 +
                                                  ((((ks << 1) + b_kh) ^ mr) << 4));
                    uint32_t b0, b1, b2, b3;
                    LDSM4(b0, b1, b2, b3, bd);
#pragma unroll
                    for (int mt = 0; mt < 2; mt++) {
                        MMA(acc[mt][p * 2],     a[mt], b0, b1);
                        MMA(acc[mt][p * 2 + 1], a[mt], b2, b3);
                    }
                }
            }
        }
        __syncthreads();
    }
    // epilogue: NHWC f32 stores (float2 per fragment half)
    size_t pixbase = (size_t)n * HW + (size_t)y0 * 64;
    int r0 = wm * 32 + (l >> 2), c0 = wn * 96 + (l & 3) * 2;
#pragma unroll
    for (int mt = 0; mt < 2; mt++)
#pragma unroll
        for (int p = 0; p < 12; p++) {
            float* d = acc[mt][p];
            size_t row = pixbase + r0 + mt * 16;
            int col = c0 + p * 8;
            *(float2*)&g_y[row * 192 + col] = make_float2(d[0], d[1]);
            *(float2*)&g_y[(row + 8) * 192 + col] = make_float2(d[2], d[3]);
        }
}

// ---------------- BN stats (deterministic) ----------------
__global__ void __launch_bounds__(192) bn_partial_kernel() {
    int c = threadIdx.x;
    int n = blockIdx.x >> 3, sl = blockIdx.x & 7;
    const float* base = g_y + ((size_t)n * HW + sl * 512) * 192 + c;
    float s = 0, q = 0;
    for (int i = 0; i < 512; i++) { float v = base[(size_t)i * 192]; s += v; q += v * v; }
    g_p1[blockIdx.x * 192 + c] = s;
    g_p2[blockIdx.x * 192 + c] = q;
}
__global__ void bn_final_kernel(const float* __restrict__ gamma, const float* __restrict__ beta) {
    int c = blockIdx.x, t = threadIdx.x;
    float s = 0, q = 0;
    for (int i = t; i < 256; i += 64) { s += g_p1[i * 192 + c]; q += g_p2[i * 192 + c]; }
    __shared__ float ss[64], sq[64];
    ss[t] = s; sq[t] = q; __syncthreads();
    for (int o = 32; o > 0; o >>= 1) {
        if (t < o) { ss[t] += ss[t + o]; sq[t] += sq[t + o]; }
        __syncthreads();
    }
    if (t == 0) {
        float m = ss[0] / 131072.0f;
        float var = sq[0] / 131072.0f - m * m;
        float sc = rsqrtf(var + 1e-5f) * gamma[c];
        g_scale[c] = sc; g_shift[c] = beta[c] - m * sc;
    }
}

// ---------------- BN apply: x1 (NCHW out) + ybh/ybl (padded NHWC bf16) ----------------
__global__ void __launch_bounds__(256) bn_apply_kernel(float* __restrict__ out) {
    __shared__ float smt[192 * 33];
    int n = blockIdx.y, px0 = blockIdx.x * 32;
    for (int i = threadIdx.x; i < 32 * 256; i += 256) {
        int pl = i >> 8, cp = i & 255;
        int g = cp >> 6, sft = cp & 63;
        size_t pix = (size_t)n * HW + px0 + pl;
        float r = 0.0f;
        if (sft < 48) {
            int c = g * 48 + sft;
            float v = g_y[pix * 192 + c];
            r = v * g_scale[c] + g_shift[c];
            smt[c * 33 + pl] = r;
        }
        __nv_bfloat16 hi = __float2bfloat16(r);
        g_ybh[pix * 256 + cp] = hi;
        g_ybl[pix * 256 + cp] = __float2bfloat16(r - __bfloat162float(hi));
    }
    __syncthreads();
    for (int j = threadIdx.x; j < 192 * 32; j += 256) {
        int c = j >> 5, pl = j & 31;
        out[((size_t)n * 512 + c) * HW + px0 + pl] = smt[c * 33 + pl];
    }
}

// ---------------- conv2: 128px x 80oc (one group), K = 9taps x 64 x {hi,lo} ----------------
// smem: A buf0 @0, A buf1 @16384, B par0 @32768, B par1 @43008; total 53248
#define C2_SMEM 53248

__device__ __forceinline__ void c2_load(uint32_t sb, int n, int y0, int g, int it, int buf, int tid) {
    int tap = it >> 1, h = it & 1;
    int ky = tap / 3, kx = tap % 3;
    const char* src = (const char*)(h ? g_ybl : g_ybh);
    uint32_t Ab = sb + (uint32_t)buf * 16384u;
#pragma unroll
    for (int ii = 0; ii < 8; ii++) {
        int lin = tid + ii * 128;
        int row = lin >> 3, j = lin & 7;
        int yy = y0 + (row >> 6) + ky - 1;
        int xg = (row & 63) + kx - 1;
        bool ok = (yy >= 0) & (yy < 64) & (xg >= 0) & (xg < 64);
        size_t off = (((size_t)n * HW + (size_t)yy * 64 + xg) * 256 + g * 64 + j * 8) * 2;
        CP16(Ab + row * 128 + ((j ^ (row & 7)) << 4), ok ? (src + off) : src, ok ? 16 : 0);
    }
    if (h == 0) {
        const char* wb = (const char*)(g_wb2 + (size_t)(tap * 4 + g) * 5120);
        uint32_t Bb = sb + 32768u + (uint32_t)(tap & 1) * 10240u;
#pragma unroll
        for (int ii = 0; ii < 5; ii++) {
            int lin = tid + ii * 128;
            CP16(Bb + lin * 16, wb + lin * 16, 16);
        }
    }
}

__global__ void __launch_bounds__(128, 3) conv2_kernel(float* __restrict__ out) {
    extern __shared__ char sm[];
    uint32_t sb = smem_u32(sm);
    int tid = threadIdx.x, l = tid & 31, wm = tid >> 5;   // 4 M-warps
    int g = blockIdx.x & 3, y0 = ((blockIdx.x >> 2) & 31) * 2, n = blockIdx.x >> 7;

    int mat = l >> 3, mr = l & 7;
    int a_rl = (mat & 1) * 8 + mr, a_kh = mat >> 1;
    int b_nl = (mat >> 1) * 8 + mr, b_kh = mat & 1;

    float acc[2][10][4];
#pragma unroll
    for (int i = 0; i < 2; i++)
#pragma unroll
        for (int jn = 0; jn < 10; jn++)
#pragma unroll
            for (int q = 0; q < 4; q++) acc[i][jn][q] = 0.0f;

    c2_load(sb, n, y0, g, 0, 0, tid); CP_COMMIT();
    for (int it = 0; it < 18; it++) {
        int buf = it & 1;
        if (it < 17) { c2_load(sb, n, y0, g, it + 1, buf ^ 1, tid); CP_COMMIT(); CP_WAIT(1); }
        else CP_WAIT(0);
        __syncthreads();
        uint32_t Ab = sb + (uint32_t)buf * 16384u;
        uint32_t Bb = sb + 32768u + (uint32_t)((it >> 1) & 1) * 10240u;
#pragma unroll
        for (int ks = 0; ks < 4; ks++) {
            uint32_t a[2][4];
#pragma unroll
            for (int mt = 0; mt < 2; mt++) {
                uint32_t ad = Ab + (uint32_t)((wm * 32 + mt * 16 + a_rl) * 128 +
                                              ((((ks << 1) + a_kh) ^ mr) << 4));
                LDSM4(a[mt][0], a[mt][1], a[mt][2], a[mt][3], ad);
            }
#pragma unroll
            for (int p = 0; p < 5; p++) {
                uint32_t bd = Bb + (uint32_t)((p * 16 + b_nl) * 128 +
                                              ((((ks << 1) + b_kh) ^ mr) << 4));
                uint32_t b0, b1, b2, b3;
                LDSM4(b0, b1, b2, b3, bd);
#pragma unroll
                for (int mt = 0; mt < 2; mt++) {
                    MMA(acc[mt][p * 2],     a[mt], b0, b1);
                    MMA(acc[mt][p * 2 + 1], a[mt], b2, b3);
                }
            }
        }
        __syncthreads();
    }
    // epilogue: NCHW stores into x2 slice
    float* ob = out + ((size_t)n * 512 + 192 + (size_t)g * 80) * HW + (size_t)y0 * 64;
    int r0 = wm * 32 + (l >> 2), c0 = (l & 3) * 2;
#pragma unroll
    for (int mt = 0; mt < 2; mt++)
#pragma unroll
        for (int nt = 0; nt < 10; nt++) {
            float* d = acc[mt][nt];
            int row = r0 + mt * 16, col = c0 + nt * 8;
            ob[(size_t)col * HW + row]           = d[0];
            ob[(size_t)(col + 1) * HW + row]     = d[1];
            ob[(size_t)col * HW + row + 8]       = d[2];
            ob[(size_t)(col + 1) * HW + row + 8] = d[3];
        }
}

// ---------------- launch ----------------
extern "C" void kernel_launch(void* const* d_in, const int* in_sizes, int n_in,
                              void* d_out, int out_size) {
    const float* x     = (const float*)d_in[0];
    const float* w1    = (const float*)d_in[1];
    const float* gamma = (const float*)d_in[2];
    const float* beta  = (const float*)d_in[3];
    const float* w2    = (const float*)d_in[4];
    float* out = (float*)d_out;

    cudaFuncSetAttribute(conv1_kernel, cudaFuncAttributeMaxDynamicSharedMemorySize, C1_SMEM);
    cudaFuncSetAttribute(conv2_kernel, cudaFuncAttributeMaxDynamicSharedMemorySize, C2_SMEM);

    lif_kernel  <<<dim3(16, 8, 8), 256>>>(x);
    prep1_kernel<<<3456, 256>>>(w1);
    prep2_kernel<<<720, 256>>>(w2);

    conv1_kernel<<<1024, 256, C1_SMEM>>>();

    bn_partial_kernel<<<256, 192>>>();
    bn_final_kernel  <<<192, 64>>>(gamma, beta);
    bn_apply_kernel  <<<dim3(128, 32), 256>>>(out);

    conv2_kernel<<<4096, 128, C2_SMEM>>>(out);
}

// round 5
// speedup vs baseline: 11.0298x; 1.5793x over previous
#include <cuda_runtime.h>
#include <cuda_fp16.h>
#include <cstdint>

#define NNI 32
#define HW  4096

// ---------------- scratch ----------------
__device__ __align__(128) __half g_spk[(size_t)NNI * HW * 256];   // spikes NHWC fp16
__device__ __align__(128) float  g_y  [(size_t)NNI * HW * 192];   // conv1 out NHWC f32
__device__ __align__(128) __half g_ybh[(size_t)NNI * HW * 256];   // BN out fp16 (4x64 padded)
__device__ __align__(128) __half g_wb1[36 * 192 * 64];            // [tap*4+chunk][192][64] swizzled
__device__ __align__(128) __half g_wb2[36 * 80 * 64];             // [tap*4+g][80][64] sign, swizzled
__device__ float g_p1[256 * 192], g_p2[256 * 192];
__device__ float g_scale[192], g_shift[192];

// ---------------- PTX helpers (sm_80-compatible only) ----------------
__device__ __forceinline__ uint32_t smem_u32(const void* p) {
    uint32_t a;
    asm("{ .reg .u64 t; cvta.to.shared.u64 t, %1; cvt.u32.u64 %0, t; }" : "=r"(a) : "l"(p));
    return a;
}
#define CP16(dst, src, nb) asm volatile("cp.async.cg.shared.global [%0], [%1], 16, %2;" :: "r"(dst), "l"(src), "r"(nb) : "memory")
#define CP_COMMIT() asm volatile("cp.async.commit_group;" ::: "memory")
#define CP_WAIT(n)  asm volatile("cp.async.wait_group %0;" :: "n"(n) : "memory")

#define LDSM4(r0, r1, r2, r3, addr) \
    asm volatile("ldmatrix.sync.aligned.m8n8.x4.shared.b16 {%0,%1,%2,%3}, [%4];" \
        : "=r"(r0), "=r"(r1), "=r"(r2), "=r"(r3) : "r"(addr))

#define MMA(d, a, b0_, b1_) \
    asm volatile("mma.sync.aligned.m16n8k16.row.col.f32.f16.f16.f32 " \
        "{%0,%1,%2,%3}, {%4,%5,%6,%7}, {%8,%9}, {%0,%1,%2,%3};" \
        : "+f"((d)[0]), "+f"((d)[1]), "+f"((d)[2]), "+f"((d)[3]) \
        : "r"((a)[0]), "r"((a)[1]), "r"((a)[2]), "r"((a)[3]), "r"(b0_), "r"(b1_))

// ---------------- LIF -> spikes NHWC fp16 ----------------
__global__ void __launch_bounds__(256) lif_kernel(const float* __restrict__ x) {
    int px = blockIdx.x * 256 + threadIdx.x;
    int cc0 = blockIdx.y * 32, b = blockIdx.z;
    float v[32];
#pragma unroll
    for (int c = 0; c < 32; c++) v[c] = 0.0f;
#pragma unroll
    for (int t = 0; t < 4; t++) {
        const float* xp = x + ((size_t)(t * 8 + b) * 256 + cc0) * HW + px;
        unsigned pk[16];
#pragma unroll
        for (int c = 0; c < 32; c++) {
            float xv = xp[(size_t)c * HW];
            float nv = v[c] + (xv - v[c]) * 0.5f;
            unsigned s = (nv >= 1.0f) ? 0x3C00u : 0u;      // fp16 1.0
            v[c] = nv - ((nv >= 1.0f) ? 1.0f : 0.0f);
            if (c & 1) pk[c >> 1] |= (s << 16); else pk[c >> 1] = s;
        }
        uint4* dst = (uint4*)(g_spk + ((size_t)(t * 8 + b) * HW + px) * 256 + cc0);
#pragma unroll
        for (int q = 0; q < 4; q++) dst[q] = make_uint4(pk[q*4], pk[q*4+1], pk[q*4+2], pk[q*4+3]);
    }
}

// ---------------- weight prep (pre-swizzled gmem tiles) ----------------
__global__ void prep1_kernel(const float* __restrict__ w1) {
    int i = blockIdx.x * 256 + threadIdx.x;           // 36*192*64
    if (i >= 36 * 192 * 64) return;
    int j = i & 63, row = (i >> 6) % 192, it = (i >> 6) / 192;
    int tap = it >> 2, c = (it & 3) * 64 + j;
    float w = w1[((size_t)row * 256 + c) * 9 + tap];
    g_wb1[(size_t)it * 12288 + row * 64 + (((j >> 3) ^ (row & 7)) * 8) + (j & 7)] = __float2half(w);
}
__global__ void prep2_kernel(const float* __restrict__ w2) {
    int i = blockIdx.x * 256 + threadIdx.x;           // 36*80*64
    if (i >= 36 * 80 * 64) return;
    int j = i & 63, row = (i >> 6) % 80, tg = (i >> 6) / 80;
    int g = tg & 3, tap = tg >> 2;
    unsigned short v = 0;
    if (j < 48) {
        float w = w2[(((size_t)(g * 80 + row)) * 48 + j) * 9 + tap];
        v = (w > 0.0f) ? 0x3C00u : ((w < 0.0f) ? 0xBC00u : 0u);
    }
    *(unsigned short*)&g_wb2[(size_t)tg * 5120 + row * 64 + (((j >> 3) ^ (row & 7)) * 8) + (j & 7)] = v;
}

// ---------------- conv1: 128px x 192oc per CTA, K = 36 x 64ch fp16 ----------------
// smem: A buf @0/16384 (16KB each), B buf @32768/57344 (24KB each); total 81920
#define C1_SMEM 81920

__device__ __forceinline__ void c1_load(uint32_t sb, int n, int y0, int it, int buf, int tid) {
    int tap = it >> 2, chunk = it & 3;
    int ky = tap / 3, kx = tap % 3;
    const char* spk = (const char*)g_spk;
    uint32_t Ab = sb + (uint32_t)buf * 16384u;
#pragma unroll
    for (int ii = 0; ii < 4; ii++) {
        int lin = tid + ii * 256;
        int row = lin >> 3, j = lin & 7;
        int yy = y0 + (row >> 6) + ky - 1;
        int xg = (row & 63) + kx - 1;
        bool ok = (yy >= 0) & (yy < 64) & (xg >= 0) & (xg < 64);
        size_t off = ((((size_t)n * HW) + (size_t)yy * 64 + xg) * 256 + chunk * 64 + j * 8) * 2;
        CP16(Ab + row * 128 + ((j ^ (row & 7)) << 4), ok ? (spk + off) : spk, ok ? 16 : 0);
    }
    const char* wb = (const char*)(g_wb1 + (size_t)it * 12288);
    uint32_t Bb = sb + 32768u + (uint32_t)buf * 24576u;
#pragma unroll
    for (int ii = 0; ii < 6; ii++) {
        int lin = tid + ii * 256;
        CP16(Bb + lin * 16, wb + lin * 16, 16);
    }
}

__global__ void __launch_bounds__(256, 1) conv1_kernel() {
    extern __shared__ char sm[];
    uint32_t sb = smem_u32(sm);
    int tid = threadIdx.x, l = tid & 31, wid = tid >> 5;
    int wm = wid & 1, wn = wid >> 1;                 // 2 M-warps x 4 N-warps
    int n = blockIdx.x >> 5, y0 = (blockIdx.x & 31) * 2;

    int mat = l >> 3, mr = l & 7;
    int a_rl = (mat & 1) * 8 + mr, a_kh = mat >> 1;
    int b_nl = (mat >> 1) * 8 + mr, b_kh = mat & 1;

    float acc[4][6][4];
#pragma unroll
    for (int i = 0; i < 4; i++)
#pragma unroll
        for (int jn = 0; jn < 6; jn++)
#pragma unroll
            for (int q = 0; q < 4; q++) acc[i][jn][q] = 0.0f;

    c1_load(sb, n, y0, 0, 0, tid); CP_COMMIT();
    for (int it = 0; it < 36; it++) {
        int buf = it & 1;
        if (it < 35) { c1_load(sb, n, y0, it + 1, buf ^ 1, tid); CP_COMMIT(); CP_WAIT(1); }
        else CP_WAIT(0);
        __syncthreads();
        uint32_t Ab = sb + (uint32_t)buf * 16384u;
        uint32_t Bb = sb + 32768u + (uint32_t)buf * 24576u;
#pragma unroll
        for (int ks = 0; ks < 4; ks++) {
            uint32_t a[4][4];
#pragma unroll
            for (int mt = 0; mt < 4; mt++) {
                uint32_t ad = Ab + (uint32_t)((wm * 64 + mt * 16 + a_rl) * 128 +
                                              ((((ks << 1) + a_kh) ^ mr) << 4));
                LDSM4(a[mt][0], a[mt][1], a[mt][2], a[mt][3], ad);
            }
#pragma unroll
            for (int p = 0; p < 3; p++) {
                uint32_t bd = Bb + (uint32_t)((wn * 48 + p * 16 + b_nl) * 128 +
                                              ((((ks << 1) + b_kh) ^ mr) << 4));
                uint32_t b0, b1, b2, b3;
                LDSM4(b0, b1, b2, b3, bd);
#pragma unroll
                for (int mt = 0; mt < 4; mt++) {
                    MMA(acc[mt][p * 2],     a[mt], b0, b1);
                    MMA(acc[mt][p * 2 + 1], a[mt], b2, b3);
                }
            }
        }
        __syncthreads();
    }
    // epilogue: NHWC f32 stores
    size_t pixbase = (size_t)n * HW + (size_t)y0 * 64;
    int c0 = wn * 48 + (l & 3) * 2;
#pragma unroll
    for (int mt = 0; mt < 4; mt++) {
        size_t row = pixbase + wm * 64 + mt * 16 + (l >> 2);
#pragma unroll
        for (int p = 0; p < 6; p++) {
            float* d = acc[mt][p];
            int col = c0 + p * 8;
            *(float2*)&g_y[row * 192 + col]       = make_float2(d[0], d[1]);
            *(float2*)&g_y[(row + 8) * 192 + col] = make_float2(d[2], d[3]);
        }
    }
}

// ---------------- BN stats (deterministic) ----------------
__global__ void __launch_bounds__(192) bn_partial_kernel() {
    int c = threadIdx.x;
    int n = blockIdx.x >> 3, sl = blockIdx.x & 7;
    const float* base = g_y + ((size_t)n * HW + sl * 512) * 192 + c;
    float s = 0, q = 0;
    for (int i = 0; i < 512; i++) { float v = base[(size_t)i * 192]; s += v; q += v * v; }
    g_p1[blockIdx.x * 192 + c] = s;
    g_p2[blockIdx.x * 192 + c] = q;
}
__global__ void bn_final_kernel(const float* __restrict__ gamma, const float* __restrict__ beta) {
    int c = blockIdx.x, t = threadIdx.x;
    float s = 0, q = 0;
    for (int i = t; i < 256; i += 64) { s += g_p1[i * 192 + c]; q += g_p2[i * 192 + c]; }
    __shared__ float ss[64], sq[64];
    ss[t] = s; sq[t] = q; __syncthreads();
    for (int o = 32; o > 0; o >>= 1) {
        if (t < o) { ss[t] += ss[t + o]; sq[t] += sq[t + o]; }
        __syncthreads();
    }
    if (t == 0) {
        float m = ss[0] / 131072.0f;
        float var = sq[0] / 131072.0f - m * m;
        float sc = rsqrtf(var + 1e-5f) * gamma[c];
        g_scale[c] = sc; g_shift[c] = beta[c] - m * sc;
    }
}

// ---------------- BN apply: x1 (NCHW out) + g_ybh (padded NHWC fp16) ----------------
__global__ void __launch_bounds__(256) bn_apply_kernel(float* __restrict__ out) {
    __shared__ float smt[192 * 33];
    int n = blockIdx.y, px0 = blockIdx.x * 32;
    for (int i = threadIdx.x; i < 32 * 256; i += 256) {
        int pl = i >> 8, cp = i & 255;
        int g = cp >> 6, sft = cp & 63;
        size_t pix = (size_t)n * HW + px0 + pl;
        float r = 0.0f;
        if (sft < 48) {
            int c = g * 48 + sft;
            float v = g_y[pix * 192 + c];
            r = v * g_scale[c] + g_shift[c];
            smt[c * 33 + pl] = r;
        }
        g_ybh[pix * 256 + cp] = __float2half(r);
    }
    __syncthreads();
    for (int j = threadIdx.x; j < 192 * 32; j += 256) {
        int c = j >> 5, pl = j & 31;
        out[((size_t)n * 512 + c) * HW + px0 + pl] = smt[c * 33 + pl];
    }
}

// ---------------- conv2: 128px x 80oc (one group), K = 9 taps x 64 fp16 ----------------
// smem: A buf @0/16384, B buf @32768/43008; total 53248
#define C2_SMEM 53248

__device__ __forceinline__ void c2_load(uint32_t sb, int n, int y0, int g, int tap, int buf, int tid) {
    int ky = tap / 3, kx = tap % 3;
    const char* src = (const char*)g_ybh;
    uint32_t Ab = sb + (uint32_t)buf * 16384u;
#pragma unroll
    for (int ii = 0; ii < 8; ii++) {
        int lin = tid + ii * 128;
        int row = lin >> 3, j = lin & 7;
        int yy = y0 + (row >> 6) + ky - 1;
        int xg = (row & 63) + kx - 1;
        bool ok = (yy >= 0) & (yy < 64) & (xg >= 0) & (xg < 64);
        size_t off = (((size_t)n * HW + (size_t)yy * 64 + xg) * 256 + g * 64 + j * 8) * 2;
        CP16(Ab + row * 128 + ((j ^ (row & 7)) << 4), ok ? (src + off) : src, ok ? 16 : 0);
    }
    const char* wb = (const char*)(g_wb2 + (size_t)(tap * 4 + g) * 5120);
    uint32_t Bb = sb + 32768u + (uint32_t)buf * 10240u;
#pragma unroll
    for (int ii = 0; ii < 5; ii++) {
        int lin = tid + ii * 128;
        CP16(Bb + lin * 16, wb + lin * 16, 16);
    }
}

__global__ void __launch_bounds__(128, 3) conv2_kernel(float* __restrict__ out) {
    extern __shared__ char sm[];
    uint32_t sb = smem_u32(sm);
    int tid = threadIdx.x, l = tid & 31, wm = tid >> 5;   // 4 M-warps
    int g = blockIdx.x & 3, y0 = ((blockIdx.x >> 2) & 31) * 2, n = blockIdx.x >> 7;

    int mat = l >> 3, mr = l & 7;
    int a_rl = (mat & 1) * 8 + mr, a_kh = mat >> 1;
    int b_nl = (mat >> 1) * 8 + mr, b_kh = mat & 1;

    float acc[2][10][4];
#pragma unroll
    for (int i = 0; i < 2; i++)
#pragma unroll
        for (int jn = 0; jn < 10; jn++)
#pragma unroll
            for (int q = 0; q < 4; q++) acc[i][jn][q] = 0.0f;

    c2_load(sb, n, y0, g, 0, 0, tid); CP_COMMIT();
    for (int it = 0; it < 9; it++) {
        int buf = it & 1;
        if (it < 8) { c2_load(sb, n, y0, g, it + 1, buf ^ 1, tid); CP_COMMIT(); CP_WAIT(1); }
        else CP_WAIT(0);
        __syncthreads();
        uint32_t Ab = sb + (uint32_t)buf * 16384u;
        uint32_t Bb = sb + 32768u + (uint32_t)buf * 10240u;
#pragma unroll
        for (int ks = 0; ks < 4; ks++) {
            uint32_t a[2][4];
#pragma unroll
            for (int mt = 0; mt < 2; mt++) {
                uint32_t ad = Ab + (uint32_t)((wm * 32 + mt * 16 + a_rl) * 128 +
                                              ((((ks << 1) + a_kh) ^ mr) << 4));
                LDSM4(a[mt][0], a[mt][1], a[mt][2], a[mt][3], ad);
            }
#pragma unroll
            for (int p = 0; p < 5; p++) {
                uint32_t bd = Bb + (uint32_t)((p * 16 + b_nl) * 128 +
                                              ((((ks << 1) + b_kh) ^ mr) << 4));
                uint32_t b0, b1, b2, b3;
                LDSM4(b0, b1, b2, b3, bd);
#pragma unroll
                for (int mt = 0; mt < 2; mt++) {
                    MMA(acc[mt][p * 2],     a[mt], b0, b1);
                    MMA(acc[mt][p * 2 + 1], a[mt], b2, b3);
                }
            }
        }
        __syncthreads();
    }
    // epilogue: NCHW stores into x2 slice
    float* ob = out + ((size_t)n * 512 + 192 + (size_t)g * 80) * HW + (size_t)y0 * 64;
    int r0 = wm * 32 + (l >> 2), c0 = (l & 3) * 2;
#pragma unroll
    for (int mt = 0; mt < 2; mt++)
#pragma unroll
        for (int nt = 0; nt < 10; nt++) {
            float* d = acc[mt][nt];
            int row = r0 + mt * 16, col = c0 + nt * 8;
            ob[(size_t)col * HW + row]           = d[0];
            ob[(size_t)(col + 1) * HW + row]     = d[1];
            ob[(size_t)col * HW + row + 8]       = d[2];
            ob[(size_t)(col + 1) * HW + row + 8] = d[3];
        }
}

// ---------------- launch ----------------
extern "C" void kernel_launch(void* const* d_in, const int* in_sizes, int n_in,
                              void* d_out, int out_size) {
    const float* x     = (const float*)d_in[0];
    const float* w1    = (const float*)d_in[1];
    const float* gamma = (const float*)d_in[2];
    const float* beta  = (const float*)d_in[3];
    const float* w2    = (const float*)d_in[4];
    float* out = (float*)d_out;

    cudaFuncSetAttribute(conv1_kernel, cudaFuncAttributeMaxDynamicSharedMemorySize, C1_SMEM);
    cudaFuncSetAttribute(conv2_kernel, cudaFuncAttributeMaxDynamicSharedMemorySize, C2_SMEM);

    lif_kernel  <<<dim3(16, 8, 8), 256>>>(x);
    prep1_kernel<<<1728, 256>>>(w1);
    prep2_kernel<<<720, 256>>>(w2);

    conv1_kernel<<<1024, 256, C1_SMEM>>>();

    bn_partial_kernel<<<256, 192>>>();
    bn_final_kernel  <<<192, 64>>>(gamma, beta);
    bn_apply_kernel  <<<dim3(128, 32), 256>>>(out);

    conv2_kernel<<<4096, 128, C2_SMEM>>>(out);
}

// round 7
// speedup vs baseline: 11.8511x; 1.0745x over previous
#include <cuda_runtime.h>
#include <cuda_fp16.h>
#include <cstdint>

#define NNI 32
#define HW  4096

// ---------------- scratch ----------------
__device__ __align__(128) __half g_spk[(size_t)NNI * HW * 256];   // spikes NHWC fp16
__device__ __align__(128) float  g_y  [(size_t)NNI * HW * 192];   // conv1 out NHWC f32
__device__ __align__(128) __half g_ybh[(size_t)NNI * HW * 256];   // BN out fp16 (4x64 padded)
__device__ __align__(128) __half g_wb1[36 * 192 * 64];            // [tap*4+chunk][192][64] swizzled
__device__ __align__(128) __half g_wb2[36 * 80 * 64];             // [tap*4+g][80][64] sign, swizzled
__device__ float g_p1[256 * 192], g_p2[256 * 192];
__device__ float g_scale[192], g_shift[192];

// ---------------- PTX helpers (sm_80-compatible only) ----------------
__device__ __forceinline__ uint32_t smem_u32(const void* p) {
    uint32_t a;
    asm("{ .reg .u64 t; cvta.to.shared.u64 t, %1; cvt.u32.u64 %0, t; }" : "=r"(a) : "l"(p));
    return a;
}
#define CP16(dst, src, nb) asm volatile("cp.async.cg.shared.global [%0], [%1], 16, %2;" :: "r"(dst), "l"(src), "r"(nb) : "memory")
#define CP_COMMIT() asm volatile("cp.async.commit_group;" ::: "memory")
#define CP_WAIT(n)  asm volatile("cp.async.wait_group %0;" :: "n"(n) : "memory")

#define LDSM4(r0, r1, r2, r3, addr) \
    asm volatile("ldmatrix.sync.aligned.m8n8.x4.shared.b16 {%0,%1,%2,%3}, [%4];" \
        : "=r"(r0), "=r"(r1), "=r"(r2), "=r"(r3) : "r"(addr))

#define MMA(d, a, b0_, b1_) \
    asm volatile("mma.sync.aligned.m16n8k16.row.col.f32.f16.f16.f32 " \
        "{%0,%1,%2,%3}, {%4,%5,%6,%7}, {%8,%9}, {%0,%1,%2,%3};" \
        : "+f"((d)[0]), "+f"((d)[1]), "+f"((d)[2]), "+f"((d)[3]) \
        : "r"((a)[0]), "r"((a)[1]), "r"((a)[2]), "r"((a)[3]), "r"(b0_), "r"(b1_))

// ---------------- LIF -> spikes NHWC fp16 ----------------
__global__ void __launch_bounds__(256) lif_kernel(const float* __restrict__ x) {
    int px = blockIdx.x * 256 + threadIdx.x;
    int cc0 = blockIdx.y * 32, b = blockIdx.z;
    float v[32];
#pragma unroll
    for (int c = 0; c < 32; c++) v[c] = 0.0f;
#pragma unroll
    for (int t = 0; t < 4; t++) {
        const float* xp = x + ((size_t)(t * 8 + b) * 256 + cc0) * HW + px;
        unsigned pk[16];
#pragma unroll
        for (int c = 0; c < 32; c++) {
            float xv = xp[(size_t)c * HW];
            float nv = v[c] + (xv - v[c]) * 0.5f;
            unsigned s = (nv >= 1.0f) ? 0x3C00u : 0u;
            v[c] = nv - ((nv >= 1.0f) ? 1.0f : 0.0f);
            if (c & 1) pk[c >> 1] |= (s << 16); else pk[c >> 1] = s;
        }
        uint4* dst = (uint4*)(g_spk + ((size_t)(t * 8 + b) * HW + px) * 256 + cc0);
#pragma unroll
        for (int q = 0; q < 4; q++) dst[q] = make_uint4(pk[q*4], pk[q*4+1], pk[q*4+2], pk[q*4+3]);
    }
}

// ---------------- weight prep (pre-swizzled gmem tiles) ----------------
__global__ void prep1_kernel(const float* __restrict__ w1) {
    int i = blockIdx.x * 256 + threadIdx.x;           // 36*192*64
    if (i >= 36 * 192 * 64) return;
    int j = i & 63, row = (i >> 6) % 192, it = (i >> 6) / 192;
    int tap = it >> 2, c = (it & 3) * 64 + j;
    float w = w1[((size_t)row * 256 + c) * 9 + tap];
    g_wb1[(size_t)it * 12288 + row * 64 + (((j >> 3) ^ (row & 7)) * 8) + (j & 7)] = __float2half(w);
}
__global__ void prep2_kernel(const float* __restrict__ w2) {
    int i = blockIdx.x * 256 + threadIdx.x;           // 36*80*64
    if (i >= 36 * 80 * 64) return;
    int j = i & 63, row = (i >> 6) % 80, tg = (i >> 6) / 80;
    int g = tg & 3, tap = tg >> 2;
    unsigned short v = 0;
    if (j < 48) {
        float w = w2[(((size_t)(g * 80 + row)) * 48 + j) * 9 + tap];
        v = (w > 0.0f) ? 0x3C00u : ((w < 0.0f) ? 0xBC00u : 0u);
    }
    *(unsigned short*)&g_wb2[(size_t)tg * 5120 + row * 64 + (((j >> 3) ^ (row & 7)) * 8) + (j & 7)] = v;
}

// ================= conv1: 128px x 192oc per CTA =================
// it = chunk*9 + tap (chunk-outer, tap-inner); B tile index = tap*4 + chunk
// A: halo tile per chunk: 264 pixel-rows x 128B = 33792B, 2 buffers
// B: 192 x 128B = 24576B, 4 stages
// smem: A0 @0, A1 @33792, B @67584 + s*24576 ; total 165888
#define C1_SMEM 165888

__device__ __forceinline__ void c1_agran(uint32_t Ab, int n, int y0, int chunk, int g) {
    int idx = g >> 3, j = g & 7;
    int hy = idx / 66, hx = idx - hy * 66;
    int y = y0 - 1 + hy, x = hx - 1;
    bool ok = ((unsigned)y < 64u) & ((unsigned)x < 64u);
    const char* spk = (const char*)g_spk;
    size_t off = ((((size_t)n * HW) + (size_t)y * 64 + x) * 256 + chunk * 64 + j * 8) * 2;
    CP16(Ab + idx * 128 + (((unsigned)(j ^ (idx & 7))) << 4), ok ? (spk + off) : spk, ok ? 16 : 0);
}

__global__ void __launch_bounds__(256, 1) conv1_kernel() {
    extern __shared__ char sm[];
    uint32_t sb = smem_u32(sm);
    int tid = threadIdx.x, l = tid & 31, wid = tid >> 5;
    int wm = wid & 1, wn = wid >> 1;                 // 2 M-warps x 4 N-warps
    int n = blockIdx.x >> 5, y0 = (blockIdx.x & 31) * 2;

    int mat = l >> 3, mr = l & 7;
    int a_rl = (mat & 1) * 8 + mr, a_kh = mat >> 1;
    int b_nl = (mat >> 1) * 8 + mr, b_kh = mat & 1;

    float acc[4][6][4];
#pragma unroll
    for (int i = 0; i < 4; i++)
#pragma unroll
        for (int jn = 0; jn < 6; jn++)
#pragma unroll
            for (int q = 0; q < 4; q++) acc[i][jn][q] = 0.0f;

    // prologue: A(chunk0), B(it=0 -> tile 0), B(it=1 -> tile tap1/chunk0 = 4)
#pragma unroll
    for (int ii = 0; ii < 9; ii++) {
        int g = tid + ii * 256;
        if (g < 2112) c1_agran(sb, n, y0, 0, g);
    }
    CP_COMMIT();
#pragma unroll
    for (int s = 0; s < 2; s++) {
        const char* wb = (const char*)g_wb1 + (size_t)(s * 4) * 24576;   // FIX: tile index tap*4+chunk = s*4
        uint32_t Bb = sb + 67584u + (uint32_t)s * 24576u;
#pragma unroll
        for (int ii = 0; ii < 6; ii++) {
            int lin = tid + ii * 256;
            CP16(Bb + lin * 16, wb + lin * 16, 16);
        }
        CP_COMMIT();
    }

    int tap = 0, c = 0;          // decomposition of it
    int tap2 = 2, c2 = 0;        // decomposition of it+2
    for (int it = 0; it < 36; it++) {
        // prefetch B(it+2)
        if (it < 34) {
            const char* wb = (const char*)g_wb1 + (size_t)(tap2 * 4 + c2) * 24576;
            uint32_t Bb = sb + 67584u + (uint32_t)((it + 2) & 3) * 24576u;
#pragma unroll
            for (int ii = 0; ii < 6; ii++) {
                int lin = tid + ii * 256;
                CP16(Bb + lin * 16, wb + lin * 16, 16);
            }
        }
        // prefetch A(c+1) spread over taps 1..6
        if (tap >= 1 && tap <= 6 && c < 3) {
            uint32_t Ab = sb + (uint32_t)((c + 1) & 1) * 33792u;
            int g0 = (tap - 1) * 352 + tid;
            c1_agran(Ab, n, y0, c + 1, g0);
            if (tid < 96) c1_agran(Ab, n, y0, c + 1, g0 + 256);
        }
        CP_COMMIT();
        CP_WAIT(2);
        __syncthreads();

        uint32_t Ahb = sb + (uint32_t)(c & 1) * 33792u;
        uint32_t Bb = sb + 67584u + (uint32_t)(it & 3) * 24576u;
        int ky = tap / 3, kx = tap - ky * 3;
        int aib = (wm + ky) * 66 + kx + a_rl;
#pragma unroll
        for (int ks = 0; ks < 4; ks++) {
            uint32_t a[4][4];
#pragma unroll
            for (int mt = 0; mt < 4; mt++) {
                int idx = aib + mt * 16;
                uint32_t ad = Ahb + (uint32_t)(idx * 128 + ((((ks << 1) + a_kh) ^ (idx & 7)) << 4));
                LDSM4(a[mt][0], a[mt][1], a[mt][2], a[mt][3], ad);
            }
#pragma unroll
            for (int p = 0; p < 3; p++) {
                int row = wn * 48 + p * 16 + b_nl;
                uint32_t bd = Bb + (uint32_t)(row * 128 + ((((ks << 1) + b_kh) ^ (row & 7)) << 4));
                uint32_t b0, b1, b2, b3;
                LDSM4(b0, b1, b2, b3, bd);
#pragma unroll
                for (int mt = 0; mt < 4; mt++) {
                    MMA(acc[mt][p * 2],     a[mt], b0, b1);
                    MMA(acc[mt][p * 2 + 1], a[mt], b2, b3);
                }
            }
        }
        if (++tap == 9) { tap = 0; c++; }
        if (++tap2 == 9) { tap2 = 0; c2++; }
    }
    // epilogue: NHWC f32 stores
    size_t pixbase = (size_t)n * HW + (size_t)y0 * 64;
    int c0 = wn * 48 + (l & 3) * 2;
#pragma unroll
    for (int mt = 0; mt < 4; mt++) {
        size_t row = pixbase + wm * 64 + mt * 16 + (l >> 2);
#pragma unroll
        for (int p = 0; p < 6; p++) {
            float* d = acc[mt][p];
            int col = c0 + p * 8;
            *(float2*)&g_y[row * 192 + col]       = make_float2(d[0], d[1]);
            *(float2*)&g_y[(row + 8) * 192 + col] = make_float2(d[2], d[3]);
        }
    }
}

// ---------------- BN stats (deterministic) ----------------
__global__ void __launch_bounds__(192) bn_partial_kernel() {
    int c = threadIdx.x;
    int n = blockIdx.x >> 3, sl = blockIdx.x & 7;
    const float* base = g_y + ((size_t)n * HW + sl * 512) * 192 + c;
    float s = 0, q = 0;
    for (int i = 0; i < 512; i++) { float v = base[(size_t)i * 192]; s += v; q += v * v; }
    g_p1[blockIdx.x * 192 + c] = s;
    g_p2[blockIdx.x * 192 + c] = q;
}
__global__ void bn_final_kernel(const float* __restrict__ gamma, const float* __restrict__ beta) {
    int c = blockIdx.x, t = threadIdx.x;
    float s = 0, q = 0;
    for (int i = t; i < 256; i += 64) { s += g_p1[i * 192 + c]; q += g_p2[i * 192 + c]; }
    __shared__ float ss[64], sq[64];
    ss[t] = s; sq[t] = q; __syncthreads();
    for (int o = 32; o > 0; o >>= 1) {
        if (t < o) { ss[t] += ss[t + o]; sq[t] += sq[t + o]; }
        __syncthreads();
    }
    if (t == 0) {
        float m = ss[0] / 131072.0f;
        float var = sq[0] / 131072.0f - m * m;
        float sc = rsqrtf(var + 1e-5f) * gamma[c];
        g_scale[c] = sc; g_shift[c] = beta[c] - m * sc;
    }
}

// ---------------- BN apply: x1 (NCHW out) + g_ybh (padded NHWC fp16) ----------------
__global__ void __launch_bounds__(256) bn_apply_kernel(float* __restrict__ out) {
    __shared__ float smt[192 * 33];
    int n = blockIdx.y, px0 = blockIdx.x * 32;
    for (int i = threadIdx.x; i < 32 * 256; i += 256) {
        int pl = i >> 8, cp = i & 255;
        int g = cp >> 6, sft = cp & 63;
        size_t pix = (size_t)n * HW + px0 + pl;
        float r = 0.0f;
        if (sft < 48) {
            int c = g * 48 + sft;
            float v = g_y[pix * 192 + c];
            r = v * g_scale[c] + g_shift[c];
            smt[c * 33 + pl] = r;
        }
        g_ybh[pix * 256 + cp] = __float2half(r);
    }
    __syncthreads();
    for (int j = threadIdx.x; j < 192 * 32; j += 256) {
        int c = j >> 5, pl = j & 31;
        out[((size_t)n * 512 + c) * HW + px0 + pl] = smt[c * 33 + pl];
    }
}

// ================= conv2: 128px x 80oc per CTA (one group) =================
// A: halo tile 264 x 128B = 33792B (single buffer, 9 taps share it)
// B: 80 x 128B = 10240B, 4 stages
// smem: A @0, B @33792 + s*10240; total 74752
#define C2_SMEM 74752

__device__ __forceinline__ void c2_agran(uint32_t Ab, int n, int y0, int grp, int g) {
    int idx = g >> 3, j = g & 7;
    int hy = idx / 66, hx = idx - hy * 66;
    int y = y0 - 1 + hy, x = hx - 1;
    bool ok = ((unsigned)y < 64u) & ((unsigned)x < 64u);
    const char* src = (const char*)g_ybh;
    size_t off = ((((size_t)n * HW) + (size_t)y * 64 + x) * 256 + grp * 64 + j * 8) * 2;
    CP16(Ab + idx * 128 + (((unsigned)(j ^ (idx & 7))) << 4), ok ? (src + off) : src, ok ? 16 : 0);
}

__global__ void __launch_bounds__(128, 3) conv2_kernel(float* __restrict__ out) {
    extern __shared__ char sm[];
    uint32_t sb = smem_u32(sm);
    int tid = threadIdx.x, l = tid & 31, wm = tid >> 5;   // 4 M-warps
    int g = blockIdx.x & 3, y0 = ((blockIdx.x >> 2) & 31) * 2, n = blockIdx.x >> 7;

    int mat = l >> 3, mr = l & 7;
    int a_rl = (mat & 1) * 8 + mr, a_kh = mat >> 1;
    int b_nl = (mat >> 1) * 8 + mr, b_kh = mat & 1;

    float acc[2][10][4];
#pragma unroll
    for (int i = 0; i < 2; i++)
#pragma unroll
        for (int jn = 0; jn < 10; jn++)
#pragma unroll
            for (int q = 0; q < 4; q++) acc[i][jn][q] = 0.0f;

    // prologue: A halo, B(0), B(1)
#pragma unroll
    for (int ii = 0; ii < 17; ii++) {
        int gg = tid + ii * 128;
        if (gg < 2112) c2_agran(sb, n, y0, g, gg);
    }
    CP_COMMIT();
#pragma unroll
    for (int s = 0; s < 2; s++) {
        const char* wb = (const char*)g_wb2 + (size_t)(s * 4 + g) * 10240;
        uint32_t Bb = sb + 33792u + (uint32_t)s * 10240u;
#pragma unroll
        for (int ii = 0; ii < 5; ii++) {
            int lin = tid + ii * 128;
            CP16(Bb + lin * 16, wb + lin * 16, 16);
        }
        CP_COMMIT();
    }

    int ry = wm >> 1, rx = (wm & 1) * 32;
    for (int it = 0; it < 9; it++) {
        if (it < 7) {
            const char* wb = (const char*)g_wb2 + (size_t)((it + 2) * 4 + g) * 10240;
            uint32_t Bb = sb + 33792u + (uint32_t)((it + 2) & 3) * 10240u;
#pragma unroll
            for (int ii = 0; ii < 5; ii++) {
                int lin = tid + ii * 128;
                CP16(Bb + lin * 16, wb + lin * 16, 16);
            }
        }
        CP_COMMIT();
        CP_WAIT(2);
        __syncthreads();

        uint32_t Bb = sb + 33792u + (uint32_t)(it & 3) * 10240u;
        int ky = it / 3, kx = it - ky * 3;
        int aib = (ry + ky) * 66 + kx + rx + a_rl;
#pragma unroll
        for (int ks = 0; ks < 4; ks++) {
            uint32_t a[2][4];
#pragma unroll
            for (int mt = 0; mt < 2; mt++) {
                int idx = aib + mt * 16;
                uint32_t ad = sb + (uint32_t)(idx * 128 + ((((ks << 1) + a_kh) ^ (idx & 7)) << 4));
                LDSM4(a[mt][0], a[mt][1], a[mt][2], a[mt][3], ad);
            }
#pragma unroll
            for (int p = 0; p < 5; p++) {
                int row = p * 16 + b_nl;
                uint32_t bd = Bb + (uint32_t)(row * 128 + ((((ks << 1) + b_kh) ^ (row & 7)) << 4));
                uint32_t b0, b1, b2, b3;
                LDSM4(b0, b1, b2, b3, bd);
#pragma unroll
                for (int mt = 0; mt < 2; mt++) {
                    MMA(acc[mt][p * 2],     a[mt], b0, b1);
                    MMA(acc[mt][p * 2 + 1], a[mt], b2, b3);
                }
            }
        }
    }
    // epilogue: NCHW stores into x2 slice
    float* ob = out + ((size_t)n * 512 + 192 + (size_t)g * 80) * HW + (size_t)y0 * 64;
    int r0 = wm * 32 + (l >> 2), c0 = (l & 3) * 2;
#pragma unroll
    for (int mt = 0; mt < 2; mt++)
#pragma unroll
        for (int nt = 0; nt < 10; nt++) {
            float* d = acc[mt][nt];
            int row = r0 + mt * 16, col = c0 + nt * 8;
            ob[(size_t)col * HW + row]           = d[0];
            ob[(size_t)(col + 1) * HW + row]     = d[1];
            ob[(size_t)col * HW + row + 8]       = d[2];
            ob[(size_t)(col + 1) * HW + row + 8] = d[3];
        }
}

// ---------------- launch ----------------
extern "C" void kernel_launch(void* const* d_in, const int* in_sizes, int n_in,
                              void* d_out, int out_size) {
    const float* x     = (const float*)d_in[0];
    const float* w1    = (const float*)d_in[1];
    const float* gamma = (const float*)d_in[2];
    const float* beta  = (const float*)d_in[3];
    const float* w2    = (const float*)d_in[4];
    float* out = (float*)d_out;

    cudaFuncSetAttribute(conv1_kernel, cudaFuncAttributeMaxDynamicSharedMemorySize, C1_SMEM);
    cudaFuncSetAttribute(conv2_kernel, cudaFuncAttributeMaxDynamicSharedMemorySize, C2_SMEM);

    lif_kernel  <<<dim3(16, 8, 8), 256>>>(x);
    prep1_kernel<<<1728, 256>>>(w1);
    prep2_kernel<<<720, 256>>>(w2);

    conv1_kernel<<<1024, 256, C1_SMEM>>>();

    bn_partial_kernel<<<256, 192>>>();
    bn_final_kernel  <<<192, 64>>>(gamma, beta);
    bn_apply_kernel  <<<dim3(128, 32), 256>>>(out);

    conv2_kernel<<<4096, 128, C2_SMEM>>>(out);
}